// round 15
// baseline (speedup 1.0000x reference)
#include <cuda_runtime.h>
#include <cuda_fp16.h>
#include <cuda_bf16.h>
#include <math.h>

// TOF PET forward projection. Grid 128^3, box [-200,200]^3, voxel 3.125mm,
// 128 samples/LOR, TOF sigma=30mm, cutoff 90mm, bin=5.
//
// R14 insight: the gather loop is SECTOR-TRAFFIC bound (~12M gathers x 32B
// L2 sectors ~= the LTS bandwidth cap; removing 25% of instructions changed
// duration by zero). So this round attacks bytes-per-sample, not
// instructions:
//  1) image converted to fp16 (values in [0,1): adds ~1.4e-5 to the
//     projection error -- invisible at tol 1e-3), and
//  2) re-laid out in 2x2x4 BRICKS so one 32B sector covers a direction-
//     agnostic neighborhood: consecutive ray samples (~0.9 voxel step)
//     share a sector ~2.5x regardless of ray direction (today only
//     z-dominant rays share; x-dominant pay 1 sector/sample).
// The projection kernel is the measured-best R6 structure verbatim (4 LORs
// per warp, branchy body, unroll 2, per-sample |u|<=UTHR && fk<=127 --
// the tail guard is required, R5 lesson), with only the gather swapped.

#define GRID_N   128
// TOF_BIN / sqrt(2*pi*TOF_SIGMA2), double-computed, rounded to f32
#define TOF_NORM 0.06649038006690422f
// sC = sqrt(log2(e)/1800); dev^2*log2e/1800 == (dev*sC)^2
#define SC_U     0.028310727f
// 90 * SC_U
#define UTHR     2.5479655f

// fp16 image copy in 2x2x4-brick layout: brick_id = bx*2048 + by*32 + bz
// (bx,by in [0,64), bz in [0,32)); local = (x&1)<<3 | (y&1)<<2 | (z&3).
__device__ __half g_img16[GRID_N * GRID_N * GRID_N];

__device__ __forceinline__ int brick_addr(int x, int y, int z)
{
    const int brick = ((x >> 1) << 11) | ((y >> 1) << 5) | (z >> 2);
    const int local = ((x & 1) << 3) | ((y & 1) << 2) | (z & 3);
    return (brick << 4) | local;
}

__global__ __launch_bounds__(256)
void convert_kernel(const float* __restrict__ image)
{
    const int idx = blockIdx.x * blockDim.x + threadIdx.x;  // linear voxel id
    const int z = idx & 127;
    const int y = (idx >> 7) & 127;
    const int x = idx >> 14;
    g_img16[brick_addr(x, y, z)] = __float2half(image[idx]);
}

__global__ __launch_bounds__(256)
void proj_kernel(const float* __restrict__ lors,
                 float* __restrict__ out,
                 int n_lors)
{
    const int warp_id = (blockIdx.x * blockDim.x + threadIdx.x) >> 5;
    const int lane    = threadIdx.x & 31;
    const int sub     = lane & 7;            // lane within 8-lane subgroup
    if (warp_id * 4 >= n_lors) return;
    int lor = warp_id * 4 + (lane >> 3);
    const bool live = (lor < n_lors);
    if (!live) lor = 0;                      // dummy work, no store

    // ---- per-LOR setup (uniform across each 8-lane subgroup) ----
    const float* l7 = lors + (size_t)lor * 7;
    const float p1x = l7[0], p1y = l7[1], p1z = l7[2];
    const float dx  = l7[3] - p1x;
    const float dy  = l7[4] - p1y;
    const float dz  = l7[5] - p1z;
    const float tof = l7[6];

    const float L = sqrtf(fmaf(dx, dx, fmaf(dy, dy, dz * dz)));

    // safe_d = where(|d| < 1e-8, 1e-8, d)  (matches reference: +eps)
    const float eps = 1e-8f;
    const float sdx = (fabsf(dx) < eps) ? eps : dx;
    const float sdy = (fabsf(dy) < eps) ? eps : dy;
    const float sdz = (fabsf(dz) < eps) ? eps : dz;

    // slab intersection via fast reciprocals (~2ulp)
    const float rx = __fdividef(1.0f, sdx);
    const float ry = __fdividef(1.0f, sdy);
    const float rz = __fdividef(1.0f, sdz);
    const float tax = (-200.0f - p1x) * rx, tbx = (200.0f - p1x) * rx;
    const float tay = (-200.0f - p1y) * ry, tby = (200.0f - p1y) * ry;
    const float taz = (-200.0f - p1z) * rz, tbz = (200.0f - p1z) * rz;

    float tmin = fmaxf(fmaxf(fminf(tax, tbx), fminf(tay, tby)), fminf(taz, tbz));
    tmin = fmaxf(tmin, 0.0f);
    float tmax = fminf(fminf(fmaxf(tax, tbx), fmaxf(tay, tby)), fmaxf(taz, tbz));
    tmax = fminf(tmax, 1.0f);

    const float valid = (tmax > tmin) ? 1.0f : 0.0f;
    const float span  = fmaxf(tmax - tmin, 0.0f);

    // ---- affine-in-k coefficients ----
    const float cs = span * 0.0078125f;          // dt per sample
    const float t0 = fmaf(0.5f, cs, tmin);       // t at k=0
    const float dL   = cs * L;                   // d(dev)/dk (>= 0)
    const float dev0 = fmaf(t0 - 0.5f, L, -tof); // dev at k=0
    const float du   = dL   * SC_U;              // u slope (>= 0)
    const float u0   = dev0 * SC_U;              // u at k=0
    const float gsx = cs * dx * 0.32f;
    const float gsy = cs * dy * 0.32f;
    const float gsz = cs * dz * 0.32f;
    const float gx0 = (fmaf(t0, dx, p1x) + 200.0f) * 0.32f;
    const float gy0 = (fmaf(t0, dy, p1y) + 200.0f) * 0.32f;
    const float gz0 = (fmaf(t0, dz, p1z) + 200.0f) * 0.32f;

    // ---- active k-window: |dev0 + fk*dL| <= 90, dL >= 0. Widened +-1.
    // Degenerate dL=0 -> rdL=inf: NaN/inf bounds collapse correctly via
    // fmaxf/fminf and F2I saturation.
    const float rdL = __fdividef(1.0f, dL);
    const float klo_f = floorf((-90.0f - dev0) * rdL) - 1.0f;
    const float khi_f = ceilf (( 90.0f - dev0) * rdL) + 1.0f;
    const int klo = (int)fmaxf(klo_f, 0.0f);    // fmaxf(NaN,0)=0
    const int khi = (int)fminf(khi_f, 127.0f);  // fminf(NaN,127)=127

    int niter = ((khi - klo) >> 3) + 1;          // <=0 when window empty
    if (!(tmax > tmin)) niter = 0;               // skip box-missing rays
    float fk = (float)(klo + sub);               // exact small ints
    float acc = 0.0f;

    #pragma unroll 2
    for (; niter > 0; --niter) {
        const float u = fmaf(fk, du, u0);
        if (fabsf(u) <= UTHR && fk <= 127.0f) {
            // lower clamp via fabs (free modifier; true coords never <= -1,
            // only rounding -eps -> +eps -> floor 0 == clamp); upper via
            // fminf(.,127.99) (128.0 -> 127 == clamp)
            const int ix = __float2int_rd(fminf(fabsf(fmaf(fk, gsx, gx0)), 127.99f));
            const int iy = __float2int_rd(fminf(fabsf(fmaf(fk, gsy, gy0)), 127.99f));
            const int iz = __float2int_rd(fminf(fabsf(fmaf(fk, gsz, gz0)), 127.99f));
            const float val = __half2float(__ldg(&g_img16[brick_addr(ix, iy, iz)]));
            const float w = exp2f(-u * u);
            acc = fmaf(val, w, acc);
        }
        fk += 8.0f;
    }

    // ---- 8-lane subgroup reduction ----
    #pragma unroll
    for (int off = 4; off > 0; off >>= 1)
        acc += __shfl_xor_sync(0xFFFFFFFFu, acc, off);

    if (sub == 0 && live) {
        const float step = span * L * (1.0f / 128.0f);
        out[lor] = acc * TOF_NORM * step * valid;
    }
}

extern "C" void kernel_launch(void* const* d_in, const int* in_sizes, int n_in,
                              void* d_out, int out_size)
{
    const float* image = (const float*)d_in[0];
    const float* lors  = (const float*)d_in[1];
    float* out = (float*)d_out;
    const int n_lors = in_sizes[1] / 7;

    const int threads = 256;

    const int cblocks = (GRID_N * GRID_N * GRID_N) / threads;
    convert_kernel<<<cblocks, threads>>>(image);

    const int n_warps = (n_lors + 3) / 4;      // 8 warps = 32 LORs/block
    const int blocks  = (n_warps * 32 + threads - 1) / threads;
    proj_kernel<<<blocks, threads>>>(lors, out, n_lors);
}

// round 16
// speedup vs baseline: 1.1251x; 1.1251x over previous
#include <cuda_runtime.h>
#include <cuda_fp16.h>
#include <cuda_bf16.h>
#include <math.h>

// TOF PET forward projection. Grid 128^3, box [-200,200]^3, voxel 3.125mm,
// 128 samples/LOR, TOF sigma=30mm, cutoff 90mm, bin=5.
//
// R14 taught: memory floor ~35us for scattered fp32 gathers (R6 sits on
// it); bricking fixed memory but its per-sample swizzle ALU cost lost more.
// R15: get the locality at ZERO per-sample cost -- keep THREE fp16 copies
// of the image, one per fastest-varying axis ([x][y][z], [z][x][y],
// [y][z][x]); each LOR picks the copy whose contiguous axis is the ray's
// dominant direction (a setup-only coefficient permutation + base-pointer
// select). Consecutive samples then walk the contiguous axis for EVERY ray
// => ~1 32B sector per 8-sample subgroup instead of up to 8. The loop body
// is bit-identical to the measured-best R6 (branchy, unroll 2, per-sample
// |u|<=UTHR && fk<=127 -- tail guard required, R5 lesson). fp16 image was
// validated in R14: rel_err 3.4458e-4.

#define GRID_N   128
#define NVOX     (GRID_N * GRID_N * GRID_N)
// TOF_BIN / sqrt(2*pi*TOF_SIGMA2), double-computed, rounded to f32
#define TOF_NORM 0.06649038006690422f
// sC = sqrt(log2(e)/1800); dev^2*log2e/1800 == (dev*sC)^2
#define SC_U     0.028310727f
// 90 * SC_U
#define UTHR     2.5479655f

// [0]: [x][y][z] (z fastest)  [1]: [z][x][y] (y fastest)  [2]: [y][z][x]
__device__ __half2 g_imgd[3][NVOX / 2];

// ---- straight fp16 convert (copy 0), fully coalesced ----
__global__ __launch_bounds__(256)
void conv0_kernel(const float2* __restrict__ in2)
{
    const int i = blockIdx.x * blockDim.x + threadIdx.x;
    const float2 f = in2[i];
    g_imgd[0][i] = __floats2half2_rn(f.x, f.y);
}

// ---- copy 1: out[z][x][y] = in[x][y][z], tiled transpose in (y,z) ----
__global__ __launch_bounds__(256)
void convY_kernel(const float* __restrict__ image)
{
    __shared__ float t[32][33];
    const int z0 = blockIdx.x * 32, y0 = blockIdx.y * 32, x = blockIdx.z;
    const int tx = threadIdx.x, ty = threadIdx.y;
    #pragma unroll
    for (int r = 0; r < 4; ++r) {
        const int y = y0 + ty + r * 8;
        t[ty + r * 8][tx] = image[x * 16384 + y * 128 + (z0 + tx)];
    }
    __syncthreads();
    __half* out = reinterpret_cast<__half*>(g_imgd[1]);
    #pragma unroll
    for (int r = 0; r < 4; ++r) {
        const int z = z0 + ty + r * 8;
        out[z * 16384 + x * 128 + (y0 + tx)] = __float2half(t[tx][ty + r * 8]);
    }
}

// ---- copy 2: out[y][z][x] = in[x][y][z], tiled transpose in (x,z) ----
__global__ __launch_bounds__(256)
void convX_kernel(const float* __restrict__ image)
{
    __shared__ float t[32][33];
    const int z0 = blockIdx.x * 32, x0 = blockIdx.y * 32, y = blockIdx.z;
    const int tx = threadIdx.x, ty = threadIdx.y;
    #pragma unroll
    for (int r = 0; r < 4; ++r) {
        const int xx = x0 + ty + r * 8;
        t[ty + r * 8][tx] = image[xx * 16384 + y * 128 + (z0 + tx)];
    }
    __syncthreads();
    __half* out = reinterpret_cast<__half*>(g_imgd[2]);
    #pragma unroll
    for (int r = 0; r < 4; ++r) {
        const int z = z0 + ty + r * 8;
        out[y * 16384 + z * 128 + (x0 + tx)] = __float2half(t[tx][ty + r * 8]);
    }
}

__global__ __launch_bounds__(256)
void proj_kernel(const float* __restrict__ lors,
                 float* __restrict__ out,
                 int n_lors)
{
    const int warp_id = (blockIdx.x * blockDim.x + threadIdx.x) >> 5;
    const int lane    = threadIdx.x & 31;
    const int sub     = lane & 7;            // lane within 8-lane subgroup
    if (warp_id * 4 >= n_lors) return;
    int lor = warp_id * 4 + (lane >> 3);
    const bool live = (lor < n_lors);
    if (!live) lor = 0;                      // dummy work, no store

    // ---- per-LOR setup (uniform across each 8-lane subgroup) ----
    const float* l7 = lors + (size_t)lor * 7;
    const float p1x = l7[0], p1y = l7[1], p1z = l7[2];
    const float dx  = l7[3] - p1x;
    const float dy  = l7[4] - p1y;
    const float dz  = l7[5] - p1z;
    const float tof = l7[6];

    const float L = sqrtf(fmaf(dx, dx, fmaf(dy, dy, dz * dz)));

    // safe_d = where(|d| < 1e-8, 1e-8, d)  (matches reference: +eps)
    const float eps = 1e-8f;
    const float sdx = (fabsf(dx) < eps) ? eps : dx;
    const float sdy = (fabsf(dy) < eps) ? eps : dy;
    const float sdz = (fabsf(dz) < eps) ? eps : dz;

    // slab intersection via fast reciprocals (~2ulp)
    const float rx = __fdividef(1.0f, sdx);
    const float ry = __fdividef(1.0f, sdy);
    const float rz = __fdividef(1.0f, sdz);
    const float tax = (-200.0f - p1x) * rx, tbx = (200.0f - p1x) * rx;
    const float tay = (-200.0f - p1y) * ry, tby = (200.0f - p1y) * ry;
    const float taz = (-200.0f - p1z) * rz, tbz = (200.0f - p1z) * rz;

    float tmin = fmaxf(fmaxf(fminf(tax, tbx), fminf(tay, tby)), fminf(taz, tbz));
    tmin = fmaxf(tmin, 0.0f);
    float tmax = fminf(fminf(fmaxf(tax, tbx), fmaxf(tay, tby)), fmaxf(taz, tbz));
    tmax = fminf(tmax, 1.0f);

    const float valid = (tmax > tmin) ? 1.0f : 0.0f;
    const float span  = fmaxf(tmax - tmin, 0.0f);

    // ---- affine-in-k coefficients ----
    const float cs = span * 0.0078125f;          // dt per sample
    const float t0 = fmaf(0.5f, cs, tmin);       // t at k=0
    const float dL   = cs * L;                   // d(dev)/dk (>= 0)
    const float dev0 = fmaf(t0 - 0.5f, L, -tof); // dev at k=0
    const float du   = dL   * SC_U;              // u slope (>= 0)
    const float u0   = dev0 * SC_U;              // u at k=0
    const float gsx = cs * dx * 0.32f;
    const float gsy = cs * dy * 0.32f;
    const float gsz = cs * dz * 0.32f;
    const float gx0 = (fmaf(t0, dx, p1x) + 200.0f) * 0.32f;
    const float gy0 = (fmaf(t0, dy, p1y) + 200.0f) * 0.32f;
    const float gz0 = (fmaf(t0, dz, p1z) + 200.0f) * 0.32f;

    // ---- dominant-axis layout selection (setup-only; zero body cost) ----
    const float adx = fabsf(dx), ady = fabsf(dy), adz = fabsf(dz);
    int sel; float gsS, g0S, gsM, g0M, gsF, g0F;
    if (adz >= adx && adz >= ady) {       // z fastest: [x][y][z]
        sel = 0; gsS = gsx; g0S = gx0; gsM = gsy; g0M = gy0; gsF = gsz; g0F = gz0;
    } else if (ady >= adx) {              // y fastest: [z][x][y]
        sel = 1; gsS = gsz; g0S = gz0; gsM = gsx; g0M = gx0; gsF = gsy; g0F = gy0;
    } else {                              // x fastest: [y][z][x]
        sel = 2; gsS = gsy; g0S = gy0; gsM = gsz; g0M = gz0; gsF = gsx; g0F = gx0;
    }
    const __half* img = reinterpret_cast<const __half*>(g_imgd[sel]);

    // ---- active k-window: |dev0 + fk*dL| <= 90, dL >= 0. Widened +-1.
    // Degenerate dL=0 -> rdL=inf: NaN/inf bounds collapse correctly via
    // fmaxf/fminf and F2I saturation.
    const float rdL = __fdividef(1.0f, dL);
    const float klo_f = floorf((-90.0f - dev0) * rdL) - 1.0f;
    const float khi_f = ceilf (( 90.0f - dev0) * rdL) + 1.0f;
    const int klo = (int)fmaxf(klo_f, 0.0f);    // fmaxf(NaN,0)=0
    const int khi = (int)fminf(khi_f, 127.0f);  // fminf(NaN,127)=127

    int niter = ((khi - klo) >> 3) + 1;          // <=0 when window empty
    if (!(tmax > tmin)) niter = 0;               // skip box-missing rays
    float fk = (float)(klo + sub);               // exact small ints
    float acc = 0.0f;

    #pragma unroll 2
    for (; niter > 0; --niter) {
        const float u = fmaf(fk, du, u0);
        if (fabsf(u) <= UTHR && fk <= 127.0f) {
            // lower clamp via fabs (free modifier; true coords never <= -1,
            // only rounding -eps -> +eps -> floor 0 == clamp); upper via
            // fminf(.,127.99) (128.0 -> 127 == clamp)
            const int iS = __float2int_rd(fminf(fabsf(fmaf(fk, gsS, g0S)), 127.99f));
            const int iM = __float2int_rd(fminf(fabsf(fmaf(fk, gsM, g0M)), 127.99f));
            const int iF = __float2int_rd(fminf(fabsf(fmaf(fk, gsF, g0F)), 127.99f));
            const float val = __half2float(__ldg(&img[iS * 16384 + iM * 128 + iF]));
            const float w = exp2f(-u * u);
            acc = fmaf(val, w, acc);
        }
        fk += 8.0f;
    }

    // ---- 8-lane subgroup reduction ----
    #pragma unroll
    for (int off = 4; off > 0; off >>= 1)
        acc += __shfl_xor_sync(0xFFFFFFFFu, acc, off);

    if (sub == 0 && live) {
        const float step = span * L * (1.0f / 128.0f);
        out[lor] = acc * TOF_NORM * step * valid;
    }
}

extern "C" void kernel_launch(void* const* d_in, const int* in_sizes, int n_in,
                              void* d_out, int out_size)
{
    const float* image = (const float*)d_in[0];
    const float* lors  = (const float*)d_in[1];
    float* out = (float*)d_out;
    const int n_lors = in_sizes[1] / 7;

    conv0_kernel<<<NVOX / 2 / 256, 256>>>((const float2*)image);
    {
        dim3 grid(4, 4, GRID_N), block(32, 8);
        convY_kernel<<<grid, block>>>(image);
        convX_kernel<<<grid, block>>>(image);
    }

    const int threads = 256;                   // 8 warps = 32 LORs/block
    const int n_warps = (n_lors + 3) / 4;
    const int blocks  = (n_warps * 32 + threads - 1) / threads;
    proj_kernel<<<blocks, threads>>>(lors, out, n_lors);
}

// round 17
// speedup vs baseline: 1.3157x; 1.1694x over previous
#include <cuda_runtime.h>
#include <cuda_bf16.h>
#include <math.h>

// TOF PET forward projection. Grid 128^3, box [-200,200]^3, voxel 3.125mm,
// 128 samples/LOR, TOF sigma=30mm, cutoff 90mm, bin=5.
//
// FOUR LORs per warp (8-lane subgroups); uniform setup SIMD across 4 LORs.
// R16 insight chain: instructions aren't binding (R13), bandwidth isn't
// binding (R14/R15); the kernel sits at the latency-hiding cliff with MLP=1
// per lane in the branchy body. So: TWO SAMPLES PER LANE per branch body
// (k and k+8, loop stride 16). Two independent LDGs per body => MLP=2,
// exposed L2 latency per sample halves; branch/loop overhead per sample
// halves. Per-sample predicates (|u|<=UTHR exact cutoff, fk<=127 tail
// guard -- R5 lesson) are applied via selects on the weights, identical
// semantics to the reference's zeroed weights.

#define GRID_N   128
// TOF_BIN / sqrt(2*pi*TOF_SIGMA2), double-computed, rounded to f32
#define TOF_NORM 0.06649038006690422f
// sC = sqrt(log2(e)/1800); dev^2*log2e/1800 == (dev*sC)^2
#define SC_U     0.028310727f
// 90 * SC_U
#define UTHR     2.5479655f

__global__ __launch_bounds__(256)
void proj_kernel(const float* __restrict__ image,
                 const float* __restrict__ lors,
                 float* __restrict__ out,
                 int n_lors)
{
    const int warp_id = (blockIdx.x * blockDim.x + threadIdx.x) >> 5;
    const int lane    = threadIdx.x & 31;
    const int sub     = lane & 7;            // lane within 8-lane subgroup
    if (warp_id * 4 >= n_lors) return;
    int lor = warp_id * 4 + (lane >> 3);
    const bool live = (lor < n_lors);
    if (!live) lor = 0;                      // dummy work, no store

    // ---- per-LOR setup (uniform across each 8-lane subgroup) ----
    const float* l7 = lors + (size_t)lor * 7;
    const float p1x = l7[0], p1y = l7[1], p1z = l7[2];
    const float dx  = l7[3] - p1x;
    const float dy  = l7[4] - p1y;
    const float dz  = l7[5] - p1z;
    const float tof = l7[6];

    const float L = sqrtf(fmaf(dx, dx, fmaf(dy, dy, dz * dz)));

    // safe_d = where(|d| < 1e-8, 1e-8, d)  (matches reference: +eps)
    const float eps = 1e-8f;
    const float sdx = (fabsf(dx) < eps) ? eps : dx;
    const float sdy = (fabsf(dy) < eps) ? eps : dy;
    const float sdz = (fabsf(dz) < eps) ? eps : dz;

    // slab intersection via fast reciprocals (~2ulp)
    const float rx = __fdividef(1.0f, sdx);
    const float ry = __fdividef(1.0f, sdy);
    const float rz = __fdividef(1.0f, sdz);
    const float tax = (-200.0f - p1x) * rx, tbx = (200.0f - p1x) * rx;
    const float tay = (-200.0f - p1y) * ry, tby = (200.0f - p1y) * ry;
    const float taz = (-200.0f - p1z) * rz, tbz = (200.0f - p1z) * rz;

    float tmin = fmaxf(fmaxf(fminf(tax, tbx), fminf(tay, tby)), fminf(taz, tbz));
    tmin = fmaxf(tmin, 0.0f);
    float tmax = fminf(fminf(fmaxf(tax, tbx), fmaxf(tay, tby)), fmaxf(taz, tbz));
    tmax = fminf(tmax, 1.0f);

    const float valid = (tmax > tmin) ? 1.0f : 0.0f;
    const float span  = fmaxf(tmax - tmin, 0.0f);

    // ---- affine-in-k coefficients ----
    const float cs = span * 0.0078125f;          // dt per sample
    const float t0 = fmaf(0.5f, cs, tmin);       // t at k=0
    const float dL   = cs * L;                   // d(dev)/dk (>= 0)
    const float dev0 = fmaf(t0 - 0.5f, L, -tof); // dev at k=0
    const float du   = dL   * SC_U;              // u slope (>= 0)
    const float u0   = dev0 * SC_U;              // u at k=0
    const float gsx = cs * dx * 0.32f;
    const float gsy = cs * dy * 0.32f;
    const float gsz = cs * dz * 0.32f;
    const float gx0 = (fmaf(t0, dx, p1x) + 200.0f) * 0.32f;
    const float gy0 = (fmaf(t0, dy, p1y) + 200.0f) * 0.32f;
    const float gz0 = (fmaf(t0, dz, p1z) + 200.0f) * 0.32f;

    // ---- active k-window: |dev0 + fk*dL| <= 90, dL >= 0. Widened +-1.
    // Degenerate dL=0 -> rdL=inf: NaN/inf bounds collapse correctly via
    // fmaxf/fminf and F2I saturation.
    const float rdL = __fdividef(1.0f, dL);
    const float klo_f = floorf((-90.0f - dev0) * rdL) - 1.0f;
    const float khi_f = ceilf (( 90.0f - dev0) * rdL) + 1.0f;
    const int klo = (int)fmaxf(klo_f, 0.0f);    // fmaxf(NaN,0)=0
    const int khi = (int)fminf(khi_f, 127.0f);  // fminf(NaN,127)=127

    int niter = ((khi - klo) >> 4) + 1;          // stride-16 blocks
    if (!(tmax > tmin)) niter = 0;               // skip box-missing rays
    float fk = (float)(klo + sub);               // exact small ints
    float acc = 0.0f;

    for (; niter > 0; --niter) {
        // two samples per lane: kA = fk, kB = fk + 8
        const float fkB = fk + 8.0f;
        const float uA = fmaf(fk,  du, u0);
        const float uB = fmaf(fkB, du, u0);
        const bool pA = (fabsf(uA) <= UTHR) && (fk  <= 127.0f);
        const bool pB = (fabsf(uB) <= UTHR) && (fkB <= 127.0f);

        if (pA || pB) {
            // lower clamp via fabs (free modifier; true coords never <= -1,
            // only rounding -eps -> +eps -> floor 0 == clamp); upper via
            // fminf(.,127.99) (128.0 -> 127 == clamp). Always in-bounds.
            const int ixA = __float2int_rd(fminf(fabsf(fmaf(fk,  gsx, gx0)), 127.99f));
            const int iyA = __float2int_rd(fminf(fabsf(fmaf(fk,  gsy, gy0)), 127.99f));
            const int izA = __float2int_rd(fminf(fabsf(fmaf(fk,  gsz, gz0)), 127.99f));
            const int ixB = __float2int_rd(fminf(fabsf(fmaf(fkB, gsx, gx0)), 127.99f));
            const int iyB = __float2int_rd(fminf(fabsf(fmaf(fkB, gsy, gy0)), 127.99f));
            const int izB = __float2int_rd(fminf(fabsf(fmaf(fkB, gsz, gz0)), 127.99f));
            // two independent gathers -> MLP=2 inside the branch
            const float valA = __ldg(&image[ixA * 16384 + iyA * 128 + izA]);
            const float valB = __ldg(&image[ixB * 16384 + iyB * 128 + izB]);
            float wA = exp2f(-uA * uA);
            float wB = exp2f(-uB * uB);
            wA = pA ? wA : 0.0f;                 // per-sample exact predicate
            wB = pB ? wB : 0.0f;
            acc = fmaf(valA, wA, acc);
            acc = fmaf(valB, wB, acc);
        }
        fk += 16.0f;
    }

    // ---- 8-lane subgroup reduction ----
    #pragma unroll
    for (int off = 4; off > 0; off >>= 1)
        acc += __shfl_xor_sync(0xFFFFFFFFu, acc, off);

    if (sub == 0 && live) {
        const float step = span * L * (1.0f / 128.0f);
        out[lor] = acc * TOF_NORM * step * valid;
    }
}

extern "C" void kernel_launch(void* const* d_in, const int* in_sizes, int n_in,
                              void* d_out, int out_size)
{
    const float* image = (const float*)d_in[0];
    const float* lors  = (const float*)d_in[1];
    float* out = (float*)d_out;
    const int n_lors = in_sizes[1] / 7;

    const int threads = 256;                       // 8 warps = 32 LORs/block
    const int n_warps = (n_lors + 3) / 4;
    const int blocks  = (n_warps * 32 + threads - 1) / threads;
    proj_kernel<<<blocks, threads>>>(image, lors, out, n_lors);
}